// round 1
// baseline (speedup 1.0000x reference)
#include <cuda_runtime.h>
#include <math.h>

// Problem sizes (fixed by the reference)
#define NB 2
#define NS 1024
#define NT (NB*NS)      // 2048 tokens
#define ND 2048         // d_model
#define NF 8192         // d_ff
#define NE 4            // experts
// top-k = 2

// Scratch (device globals; no allocations allowed)
__device__ float g_gatew[NE*NT];          // gate weight per (expert, token); 0 if unselected
__device__ int   g_counts[NE];            // tokens routed to each expert
__device__ int   g_lists[NE*NT];          // token indices per expert (compacted)
__device__ float g_GH[67108864];          // [NE][NT][NF] fp32 (256 MB): G then H=silu(G)*U in place

// ---------------------------------------------------------------------------
// Zero output + counts
// ---------------------------------------------------------------------------
__global__ void zero_kernel(float* __restrict__ out) {
    size_t n = (size_t)NT * ND;
    for (size_t i = blockIdx.x * (size_t)blockDim.x + threadIdx.x; i < n;
         i += (size_t)gridDim.x * blockDim.x)
        out[i] = 0.f;
    if (blockIdx.x == 0 && threadIdx.x < NE) g_counts[threadIdx.x] = 0;
}

// ---------------------------------------------------------------------------
// Router: logits = x @ Wr, softmax over E=4, top-2 -> gate weights
// One block (256 thr) per token.
// ---------------------------------------------------------------------------
__global__ void router_kernel(const float* __restrict__ x, const float* __restrict__ Wr) {
    int t = blockIdx.x;
    const float* xr = x + (size_t)t * ND;
    float acc[NE] = {0.f, 0.f, 0.f, 0.f};
    for (int d = threadIdx.x; d < ND; d += blockDim.x) {
        float xv = xr[d];
        float4 w = *(const float4*)(Wr + d * NE);
        acc[0] += xv * w.x; acc[1] += xv * w.y; acc[2] += xv * w.z; acc[3] += xv * w.w;
    }
    __shared__ float sred[NE][8];
    int lane = threadIdx.x & 31, wid = threadIdx.x >> 5;
    #pragma unroll
    for (int e = 0; e < NE; e++) {
        float s = acc[e];
        #pragma unroll
        for (int off = 16; off > 0; off >>= 1) s += __shfl_down_sync(0xffffffffu, s, off);
        if (lane == 0) sred[e][wid] = s;
    }
    __syncthreads();
    if (threadIdx.x == 0) {
        float l[NE];
        #pragma unroll
        for (int e = 0; e < NE; e++) {
            float s = 0.f;
            #pragma unroll
            for (int w = 0; w < 8; w++) s += sred[e][w];
            l[e] = s;
        }
        float mx = fmaxf(fmaxf(l[0], l[1]), fmaxf(l[2], l[3]));
        float ex[NE], ssum = 0.f;
        #pragma unroll
        for (int e = 0; e < NE; e++) { ex[e] = expf(l[e] - mx); ssum += ex[e]; }
        float p[NE];
        #pragma unroll
        for (int e = 0; e < NE; e++) p[e] = ex[e] / ssum;
        // top-2 (ties -> lower index, matching lax.top_k)
        int i1 = 0;
        #pragma unroll
        for (int e = 1; e < NE; e++) if (p[e] > p[i1]) i1 = e;
        int i2 = -1;
        #pragma unroll
        for (int e = 0; e < NE; e++)
            if (e != i1 && (i2 < 0 || p[e] > p[i2])) i2 = e;
        #pragma unroll
        for (int e = 0; e < NE; e++)
            g_gatew[e * NT + t] = (e == i1 || e == i2) ? p[e] : 0.f;
    }
}

// ---------------------------------------------------------------------------
// Compact token lists per expert
// ---------------------------------------------------------------------------
__global__ void compact_kernel() {
    for (int t = threadIdx.x; t < NT; t += blockDim.x) {
        #pragma unroll
        for (int e = 0; e < NE; e++) {
            if (g_gatew[e * NT + t] > 0.f) {
                int p = atomicAdd(&g_counts[e], 1);
                g_lists[e * NT + p] = t;
            }
        }
    }
}

// ---------------------------------------------------------------------------
// Tiled fp32 GEMM, 128x128 block tile, BK=16, 8x8 per-thread, 256 threads.
// MODE 0: G = gather(X) @ Wg[e]           -> store into g_GH
// MODE 1: U = gather(X) @ Wu[e]           -> g_GH = silu(g_GH) * U  (in place)
// MODE 2: Y = g_GH      @ Wd[e]           -> out[tok] += gate_w * Y (atomic)
// ---------------------------------------------------------------------------
template<int MODE>
__global__ __launch_bounds__(256) void moe_gemm(const float* __restrict__ X,
                                                const float* __restrict__ W,
                                                float* __restrict__ OUT) {
    constexpr int BM = 128, BN = 128, BK = 16;
    constexpr int Kdim = (MODE == 2) ? NF : ND;
    constexpr int Ndim = (MODE == 2) ? ND : NF;

    const int e  = blockIdx.z;
    const int Me = g_counts[e];
    const int m0 = blockIdx.y * BM;
    if (m0 >= Me) return;
    const int n0 = blockIdx.x * BN;

    const float* Bp = W + (size_t)e * Kdim * Ndim + n0;

    __shared__ float As[BK][BM];
    __shared__ float Bs[BK][BN];

    const int tid  = threadIdx.x;
    const int arow = tid & 127;        // A row this thread loads
    const int ak0  = (tid >> 7) * 4;   // k offset: 0 or 4 (also +8)
    const int br0  = tid >> 5;         // B row 0..7 (also +8)
    const int bc   = (tid & 31) * 4;   // B col (float4)

    const int  m_a    = m0 + arow;
    const bool avalid = (m_a < Me);

    const float* Ar;
    if (MODE == 2) {
        Ar = g_GH + (size_t)e * NT * NF + (size_t)m_a * NF;
    } else {
        int tok = avalid ? g_lists[e * NT + m_a] : 0;
        Ar = X + (size_t)tok * ND;
    }

    const int tx = tid & 15;
    const int ty = tid >> 4;

    float acc[8][8];
    #pragma unroll
    for (int i = 0; i < 8; i++)
        #pragma unroll
        for (int j = 0; j < 8; j++) acc[i][j] = 0.f;

    for (int kt = 0; kt < Kdim; kt += BK) {
        float4 a0 = make_float4(0.f, 0.f, 0.f, 0.f), a1 = a0;
        if (avalid) {
            a0 = *(const float4*)(Ar + kt + ak0);
            a1 = *(const float4*)(Ar + kt + ak0 + 8);
        }
        As[ak0 + 0][arow] = a0.x; As[ak0 + 1][arow] = a0.y;
        As[ak0 + 2][arow] = a0.z; As[ak0 + 3][arow] = a0.w;
        As[ak0 + 8][arow] = a1.x; As[ak0 + 9][arow] = a1.y;
        As[ak0 + 10][arow] = a1.z; As[ak0 + 11][arow] = a1.w;

        float4 b0 = *(const float4*)(Bp + (size_t)(kt + br0) * Ndim + bc);
        float4 b1 = *(const float4*)(Bp + (size_t)(kt + br0 + 8) * Ndim + bc);
        *(float4*)&Bs[br0][bc]     = b0;
        *(float4*)&Bs[br0 + 8][bc] = b1;
        __syncthreads();

        #pragma unroll
        for (int k = 0; k < BK; k++) {
            float4 av0 = *(const float4*)&As[k][ty * 8];
            float4 av1 = *(const float4*)&As[k][ty * 8 + 4];
            float4 bv0 = *(const float4*)&Bs[k][tx * 8];
            float4 bv1 = *(const float4*)&Bs[k][tx * 8 + 4];
            float a[8] = {av0.x, av0.y, av0.z, av0.w, av1.x, av1.y, av1.z, av1.w};
            float b[8] = {bv0.x, bv0.y, bv0.z, bv0.w, bv1.x, bv1.y, bv1.z, bv1.w};
            #pragma unroll
            for (int i = 0; i < 8; i++)
                #pragma unroll
                for (int j = 0; j < 8; j++)
                    acc[i][j] += a[i] * b[j];
        }
        __syncthreads();
    }

    // Epilogue
    #pragma unroll
    for (int i = 0; i < 8; i++) {
        int m = m0 + ty * 8 + i;
        if (m >= Me) continue;
        if (MODE == 0) {
            float* dst = g_GH + (size_t)e * NT * NF + (size_t)m * NF + n0 + tx * 8;
            *(float4*)dst       = make_float4(acc[i][0], acc[i][1], acc[i][2], acc[i][3]);
            *(float4*)(dst + 4) = make_float4(acc[i][4], acc[i][5], acc[i][6], acc[i][7]);
        } else if (MODE == 1) {
            float* dst = g_GH + (size_t)e * NT * NF + (size_t)m * NF + n0 + tx * 8;
            #pragma unroll
            for (int j = 0; j < 8; j++) {
                float g  = dst[j];
                float sg = 1.f / (1.f + expf(-g));
                dst[j]   = g * sg * acc[i][j];   // silu(g) * u
            }
        } else {
            int   tok = g_lists[e * NT + m];
            float w   = g_gatew[e * NT + tok];
            float* dst = OUT + (size_t)tok * ND + n0 + tx * 8;
            #pragma unroll
            for (int j = 0; j < 8; j++)
                atomicAdd(dst + j, w * acc[i][j]);
        }
    }
}

// ---------------------------------------------------------------------------
extern "C" void kernel_launch(void* const* d_in, const int* in_sizes, int n_in,
                              void* d_out, int out_size) {
    const float* x  = (const float*)d_in[0];  // [2,1024,2048]
    const float* Wr = (const float*)d_in[1];  // [2048,4]
    const float* Wg = (const float*)d_in[2];  // [4,2048,8192]
    const float* Wu = (const float*)d_in[3];  // [4,2048,8192]
    const float* Wd = (const float*)d_in[4];  // [4,8192,2048]
    float* out = (float*)d_out;               // [2,1024,2048]

    zero_kernel<<<2048, 256>>>(out);
    router_kernel<<<NT, 256>>>(x, Wr);
    compact_kernel<<<1, 256>>>();

    dim3 g1(NF / 128, NT / 128, NE);          // 64 x 16 x 4
    moe_gemm<0><<<g1, 256>>>(x, Wg, nullptr); // G = X@Wg
    moe_gemm<1><<<g1, 256>>>(x, Wu, nullptr); // H = silu(G)*(X@Wu)
    dim3 g2(ND / 128, NT / 128, NE);          // 16 x 16 x 4
    moe_gemm<2><<<g2, 256>>>(x, Wd, out);     // out += w * H@Wd
}

// round 2
// speedup vs baseline: 3.1701x; 3.1701x over previous
#include <cuda_runtime.h>
#include <math.h>

#define NB 2
#define NS 1024
#define NT (NB*NS)      // 2048 tokens
#define ND 2048         // d_model
#define NF 8192         // d_ff
#define NE 4            // experts

// Scratch (device globals; no allocations allowed)
__device__ float g_gatew[NE*NT];     // gate weight per (expert, token); 0 if unselected
__device__ int   g_counts[NE];       // tokens routed to each expert
__device__ int   g_lists[NE*NT];     // token indices per expert (compacted)
__device__ float g_H[(size_t)NE*NT*NF]; // [NE][NT][NF] fp32: H = silu(G)*U  (rows >= Me stay 0)

// ---------------------------------------------------------------------------
__device__ __forceinline__ unsigned f2tf(float f) {
    unsigned u;
    asm("cvt.rna.tf32.f32 %0, %1;" : "=r"(u) : "f"(f));
    return u;
}

__device__ __forceinline__ void mma8(float c[4], const unsigned a[4], const unsigned b[2]) {
    asm volatile(
        "mma.sync.aligned.m16n8k8.row.col.f32.tf32.tf32.f32 "
        "{%0,%1,%2,%3}, {%4,%5,%6,%7}, {%8,%9}, {%0,%1,%2,%3};"
        : "+f"(c[0]), "+f"(c[1]), "+f"(c[2]), "+f"(c[3])
        : "r"(a[0]), "r"(a[1]), "r"(a[2]), "r"(a[3]), "r"(b[0]), "r"(b[1]));
}

// ---------------------------------------------------------------------------
__global__ void zero_kernel(float* __restrict__ out) {
    size_t n = (size_t)NT * ND;
    for (size_t i = blockIdx.x * (size_t)blockDim.x + threadIdx.x; i < n;
         i += (size_t)gridDim.x * blockDim.x)
        out[i] = 0.f;
    if (blockIdx.x == 0 && threadIdx.x < NE) g_counts[threadIdx.x] = 0;
}

// ---------------------------------------------------------------------------
// Router: softmax(x@Wr) top-2 (one block / token)
// ---------------------------------------------------------------------------
__global__ void router_kernel(const float* __restrict__ x, const float* __restrict__ Wr) {
    int t = blockIdx.x;
    const float* xr = x + (size_t)t * ND;
    float acc[NE] = {0.f, 0.f, 0.f, 0.f};
    for (int d = threadIdx.x; d < ND; d += blockDim.x) {
        float xv = xr[d];
        float4 w = *(const float4*)(Wr + d * NE);
        acc[0] += xv * w.x; acc[1] += xv * w.y; acc[2] += xv * w.z; acc[3] += xv * w.w;
    }
    __shared__ float sred[NE][8];
    int lane = threadIdx.x & 31, wid = threadIdx.x >> 5;
    #pragma unroll
    for (int e = 0; e < NE; e++) {
        float s = acc[e];
        #pragma unroll
        for (int off = 16; off > 0; off >>= 1) s += __shfl_down_sync(0xffffffffu, s, off);
        if (lane == 0) sred[e][wid] = s;
    }
    __syncthreads();
    if (threadIdx.x == 0) {
        float l[NE];
        #pragma unroll
        for (int e = 0; e < NE; e++) {
            float s = 0.f;
            #pragma unroll
            for (int w = 0; w < 8; w++) s += sred[e][w];
            l[e] = s;
        }
        float mx = fmaxf(fmaxf(l[0], l[1]), fmaxf(l[2], l[3]));
        float ex[NE], ssum = 0.f;
        #pragma unroll
        for (int e = 0; e < NE; e++) { ex[e] = expf(l[e] - mx); ssum += ex[e]; }
        float p[NE];
        #pragma unroll
        for (int e = 0; e < NE; e++) p[e] = ex[e] / ssum;
        int i1 = 0;
        #pragma unroll
        for (int e = 1; e < NE; e++) if (p[e] > p[i1]) i1 = e;
        int i2 = -1;
        #pragma unroll
        for (int e = 0; e < NE; e++)
            if (e != i1 && (i2 < 0 || p[e] > p[i2])) i2 = e;
        #pragma unroll
        for (int e = 0; e < NE; e++)
            g_gatew[e * NT + t] = (e == i1 || e == i2) ? p[e] : 0.f;
    }
}

__global__ void compact_kernel() {
    for (int t = threadIdx.x; t < NT; t += blockDim.x) {
        #pragma unroll
        for (int e = 0; e < NE; e++) {
            if (g_gatew[e * NT + t] > 0.f) {
                int p = atomicAdd(&g_counts[e], 1);
                g_lists[e * NT + p] = t;
            }
        }
    }
}

// ---------------------------------------------------------------------------
// Fused gate+up GEMM (TF32 mma): H = silu(gather(X)@Wg) * (gather(X)@Wu)
// Block tile: 128(M) x 64(N, per matrix) x 16(K). 8 warps, 4x2 -> 32x32 warptile.
// ---------------------------------------------------------------------------
__global__ __launch_bounds__(256) void gateup_kernel(const float* __restrict__ X,
                                                     const float* __restrict__ Wg,
                                                     const float* __restrict__ Wu) {
    constexpr int BM = 128, BN = 64, BK = 16;
    const int e  = blockIdx.z;
    const int Me = g_counts[e];
    const int m0 = blockIdx.y * BM;
    if (m0 >= Me) return;
    const int n0 = blockIdx.x * BN;

    __shared__ unsigned As[BK][BM + 4];    // stride 132 -> conflict-free frags
    __shared__ unsigned Bgs[BK][BN + 4];   // stride 68
    __shared__ unsigned Bus[BK][BN + 4];

    const int tid  = threadIdx.x;
    const int warp = tid >> 5;
    const int lane = tid & 31;
    const int g4   = lane >> 2;           // groupID 0..7
    const int t4   = lane & 3;            // thread-in-group
    const int wm   = warp >> 1;           // 0..3
    const int wn   = warp & 1;            // 0..1

    // A load: thread t loads row (t&127), k-chunk (t>>7)*8 .. +7 (two float4)
    const int arow = tid & 127;
    const int akc  = (tid >> 7) * 8;
    int m_a = m0 + arow;
    if (m_a >= NT) m_a = NT - 1;
    const int tok = g_lists[e * NT + m_a];
    const float* Arow = X + (size_t)tok * ND;

    // B load: row br (0..15), cols bc..bc+3
    const int br = tid >> 4;
    const int bc = (tid & 15) * 4;
    const float* Bgp = Wg + (size_t)e * ND * NF + (size_t)br * NF + n0 + bc;
    const float* Bup = Wu + (size_t)e * ND * NF + (size_t)br * NF + n0 + bc;

    float accG[2][4][4], accU[2][4][4];
    #pragma unroll
    for (int i = 0; i < 2; i++)
        #pragma unroll
        for (int j = 0; j < 4; j++)
            #pragma unroll
            for (int k = 0; k < 4; k++) { accG[i][j][k] = 0.f; accU[i][j][k] = 0.f; }

    float4 ra0, ra1, rg, ru;
    // prologue load
    ra0 = *(const float4*)(Arow + akc);
    ra1 = *(const float4*)(Arow + akc + 4);
    rg  = *(const float4*)Bgp;
    ru  = *(const float4*)Bup;

    for (int kt = 0; kt < ND; kt += BK) {
        // store staged tile (with fp32->tf32 RNE convert)
        As[akc + 0][arow] = f2tf(ra0.x); As[akc + 1][arow] = f2tf(ra0.y);
        As[akc + 2][arow] = f2tf(ra0.z); As[akc + 3][arow] = f2tf(ra0.w);
        As[akc + 4][arow] = f2tf(ra1.x); As[akc + 5][arow] = f2tf(ra1.y);
        As[akc + 6][arow] = f2tf(ra1.z); As[akc + 7][arow] = f2tf(ra1.w);
        *(uint4*)&Bgs[br][bc] = make_uint4(f2tf(rg.x), f2tf(rg.y), f2tf(rg.z), f2tf(rg.w));
        *(uint4*)&Bus[br][bc] = make_uint4(f2tf(ru.x), f2tf(ru.y), f2tf(ru.z), f2tf(ru.w));
        __syncthreads();

        if (kt + BK < ND) {   // issue next tile's loads early
            ra0 = *(const float4*)(Arow + kt + BK + akc);
            ra1 = *(const float4*)(Arow + kt + BK + akc + 4);
            rg  = *(const float4*)(Bgp + (size_t)(kt + BK) * NF);
            ru  = *(const float4*)(Bup + (size_t)(kt + BK) * NF);
        }

        #pragma unroll
        for (int ks = 0; ks < BK; ks += 8) {
            unsigned a[2][4];
            #pragma unroll
            for (int mi = 0; mi < 2; mi++) {
                int mb = wm * 32 + mi * 16 + g4;
                a[mi][0] = As[ks + t4][mb];
                a[mi][1] = As[ks + t4][mb + 8];
                a[mi][2] = As[ks + t4 + 4][mb];
                a[mi][3] = As[ks + t4 + 4][mb + 8];
            }
            #pragma unroll
            for (int ni = 0; ni < 4; ni++) {
                int nb = wn * 32 + ni * 8 + g4;
                unsigned bg[2] = { Bgs[ks + t4][nb], Bgs[ks + t4 + 4][nb] };
                unsigned bu[2] = { Bus[ks + t4][nb], Bus[ks + t4 + 4][nb] };
                #pragma unroll
                for (int mi = 0; mi < 2; mi++) {
                    mma8(accG[mi][ni], a[mi], bg);
                    mma8(accU[mi][ni], a[mi], bu);
                }
            }
        }
        __syncthreads();
    }

    // Epilogue: H = silu(G)*U
    #pragma unroll
    for (int mi = 0; mi < 2; mi++) {
        #pragma unroll
        for (int half = 0; half < 2; half++) {
            int m = m0 + wm * 32 + mi * 16 + g4 + half * 8;
            if (m >= Me) continue;
            float* Hrow = g_H + ((size_t)e * NT + m) * NF + n0 + wn * 32;
            #pragma unroll
            for (int ni = 0; ni < 4; ni++) {
                float gv0 = accG[mi][ni][half * 2],     uv0 = accU[mi][ni][half * 2];
                float gv1 = accG[mi][ni][half * 2 + 1], uv1 = accU[mi][ni][half * 2 + 1];
                float h0 = gv0 / (1.f + expf(-gv0)) * uv0;
                float h1 = gv1 / (1.f + expf(-gv1)) * uv1;
                *(float2*)(Hrow + ni * 8 + 2 * t4) = make_float2(h0, h1);
            }
        }
    }
}

// ---------------------------------------------------------------------------
// Down GEMM (TF32 mma): out[tok] += gate_w * (H @ Wd[e])
// Block tile: 128x128x16. 8 warps, 4x2 -> 32x64 warptile.
// ---------------------------------------------------------------------------
__global__ __launch_bounds__(256) void down_kernel(const float* __restrict__ Wd,
                                                   float* __restrict__ OUT) {
    constexpr int BM = 128, BN = 128, BK = 16;
    const int e  = blockIdx.z;
    const int Me = g_counts[e];
    const int m0 = blockIdx.y * BM;
    if (m0 >= Me) return;
    const int n0 = blockIdx.x * BN;

    __shared__ unsigned As[BK][BM + 4];   // stride 132
    __shared__ unsigned Bs[BK][BN + 4];   // stride 132

    const int tid  = threadIdx.x;
    const int warp = tid >> 5;
    const int lane = tid & 31;
    const int g4   = lane >> 2;
    const int t4   = lane & 3;
    const int wm   = warp >> 1;           // 0..3
    const int wn   = warp & 1;            // 0..1

    const int arow = tid & 127;
    const int akc  = (tid >> 7) * 8;
    const float* Arow = g_H + ((size_t)e * NT + (m0 + arow)) * NF;  // rows>=Me are zeros

    const int br = tid >> 4;
    const int bc = (tid & 15) * 8;
    const float* Bp = Wd + (size_t)e * NF * ND + (size_t)br * ND + n0 + bc;

    float acc[2][8][4];
    #pragma unroll
    for (int i = 0; i < 2; i++)
        #pragma unroll
        for (int j = 0; j < 8; j++)
            #pragma unroll
            for (int k = 0; k < 4; k++) acc[i][j][k] = 0.f;

    float4 ra0, ra1, rb0, rb1;
    ra0 = *(const float4*)(Arow + akc);
    ra1 = *(const float4*)(Arow + akc + 4);
    rb0 = *(const float4*)Bp;
    rb1 = *(const float4*)(Bp + 4);

    for (int kt = 0; kt < NF; kt += BK) {
        As[akc + 0][arow] = f2tf(ra0.x); As[akc + 1][arow] = f2tf(ra0.y);
        As[akc + 2][arow] = f2tf(ra0.z); As[akc + 3][arow] = f2tf(ra0.w);
        As[akc + 4][arow] = f2tf(ra1.x); As[akc + 5][arow] = f2tf(ra1.y);
        As[akc + 6][arow] = f2tf(ra1.z); As[akc + 7][arow] = f2tf(ra1.w);
        *(uint4*)&Bs[br][bc]     = make_uint4(f2tf(rb0.x), f2tf(rb0.y), f2tf(rb0.z), f2tf(rb0.w));
        *(uint4*)&Bs[br][bc + 4] = make_uint4(f2tf(rb1.x), f2tf(rb1.y), f2tf(rb1.z), f2tf(rb1.w));
        __syncthreads();

        if (kt + BK < NF) {
            ra0 = *(const float4*)(Arow + kt + BK + akc);
            ra1 = *(const float4*)(Arow + kt + BK + akc + 4);
            rb0 = *(const float4*)(Bp + (size_t)(kt + BK) * ND);
            rb1 = *(const float4*)(Bp + (size_t)(kt + BK) * ND + 4);
        }

        #pragma unroll
        for (int ks = 0; ks < BK; ks += 8) {
            unsigned a[2][4];
            #pragma unroll
            for (int mi = 0; mi < 2; mi++) {
                int mb = wm * 32 + mi * 16 + g4;
                a[mi][0] = As[ks + t4][mb];
                a[mi][1] = As[ks + t4][mb + 8];
                a[mi][2] = As[ks + t4 + 4][mb];
                a[mi][3] = As[ks + t4 + 4][mb + 8];
            }
            #pragma unroll
            for (int ni = 0; ni < 8; ni++) {
                int nb = wn * 64 + ni * 8 + g4;
                unsigned b[2] = { Bs[ks + t4][nb], Bs[ks + t4 + 4][nb] };
                #pragma unroll
                for (int mi = 0; mi < 2; mi++)
                    mma8(acc[mi][ni], a[mi], b);
            }
        }
        __syncthreads();
    }

    // Epilogue: atomic combine (each output element gets exactly 2 contributions)
    #pragma unroll
    for (int mi = 0; mi < 2; mi++) {
        #pragma unroll
        for (int half = 0; half < 2; half++) {
            int m = m0 + wm * 32 + mi * 16 + g4 + half * 8;
            if (m >= Me) continue;
            int tok = g_lists[e * NT + m];
            float w = g_gatew[e * NT + tok];
            float* dst = OUT + (size_t)tok * ND + n0 + wn * 64;
            #pragma unroll
            for (int ni = 0; ni < 8; ni++) {
                atomicAdd(dst + ni * 8 + 2 * t4,     w * acc[mi][ni][half * 2]);
                atomicAdd(dst + ni * 8 + 2 * t4 + 1, w * acc[mi][ni][half * 2 + 1]);
            }
        }
    }
}

// ---------------------------------------------------------------------------
extern "C" void kernel_launch(void* const* d_in, const int* in_sizes, int n_in,
                              void* d_out, int out_size) {
    const float* x  = (const float*)d_in[0];  // [2,1024,2048]
    const float* Wr = (const float*)d_in[1];  // [2048,4]
    const float* Wg = (const float*)d_in[2];  // [4,2048,8192]
    const float* Wu = (const float*)d_in[3];  // [4,2048,8192]
    const float* Wd = (const float*)d_in[4];  // [4,8192,2048]
    float* out = (float*)d_out;               // [2,1024,2048]

    zero_kernel<<<2048, 256>>>(out);
    router_kernel<<<NT, 256>>>(x, Wr);
    compact_kernel<<<1, 256>>>();

    dim3 g1(NF / 64, NT / 128, NE);           // 128 x 16 x 4
    gateup_kernel<<<g1, 256>>>(x, Wg, Wu);
    dim3 g2(ND / 128, NT / 128, NE);          // 16 x 16 x 4
    down_kernel<<<g2, 256>>>(Wd, out);
}

// round 5
// speedup vs baseline: 5.0171x; 1.5827x over previous
#include <cuda_runtime.h>
#include <math.h>
#include <stdint.h>

#define NB 2
#define NS 1024
#define NT (NB*NS)      // 2048 tokens
#define ND 2048
#define NF 8192
#define NE 4

// ---------------- persistent scratch (device globals) ----------------------
__device__ float g_gatew[NE*NT];
__device__ int   g_counts[NE];
__device__ int   g_lists[NE*NT];
__device__ float g_H [(size_t)NE*NT*NF];             // H = silu(G)*U, tf32-rounded; rows>=Me stay 0
__device__ float g_Xr[(size_t)NT*ND];                // x, tf32-rounded
__device__ float g_Wgr[(size_t)NE*ND*NF];            // weights, tf32-rounded (input layout)
__device__ float g_Wur[(size_t)NE*ND*NF];
__device__ float g_Wdr[(size_t)NE*NF*ND];

// ---------------- helpers ---------------------------------------------------
__device__ __forceinline__ uint32_t smem_u32(const void* p) {
    uint32_t a;
    asm("{ .reg .u64 t; cvta.to.shared.u64 t, %1; cvt.u32.u64 %0, t; }" : "=r"(a) : "l"(p));
    return a;
}
__device__ __forceinline__ unsigned f2tf(float f) {
    unsigned u; asm("cvt.rna.tf32.f32 %0, %1;" : "=r"(u) : "f"(f)); return u;
}
__device__ __forceinline__ float tf32r(float f) { return __uint_as_float(f2tf(f)); }

__device__ __forceinline__ void cpa16(uint32_t dst, const float* src) {
    asm volatile("cp.async.cg.shared.global [%0], [%1], 16;" :: "r"(dst), "l"(src));
}
__device__ __forceinline__ void cpa_commit() { asm volatile("cp.async.commit_group;"); }
__device__ __forceinline__ void cpa_wait1()  { asm volatile("cp.async.wait_group 1;"); }

__device__ __forceinline__ void mma8(float c[4], const unsigned a[4], const unsigned b[2]) {
    asm volatile(
        "mma.sync.aligned.m16n8k8.row.col.f32.tf32.tf32.f32 "
        "{%0,%1,%2,%3}, {%4,%5,%6,%7}, {%8,%9}, {%0,%1,%2,%3};"
        : "+f"(c[0]), "+f"(c[1]), "+f"(c[2]), "+f"(c[3])
        : "r"(a[0]), "r"(a[1]), "r"(a[2]), "r"(a[3]), "r"(b[0]), "r"(b[1]));
}

// ---------------- trivial kernels -------------------------------------------
__global__ void zero_kernel(float* __restrict__ out) {
    size_t n = (size_t)NT * ND;
    for (size_t i = blockIdx.x * (size_t)blockDim.x + threadIdx.x; i < n;
         i += (size_t)gridDim.x * blockDim.x) out[i] = 0.f;
    if (blockIdx.x == 0 && threadIdx.x < NE) g_counts[threadIdx.x] = 0;
}

__global__ void round_copy(const float* __restrict__ src, float* __restrict__ dst, size_t n4) {
    for (size_t i = blockIdx.x * (size_t)blockDim.x + threadIdx.x; i < n4;
         i += (size_t)gridDim.x * blockDim.x) {
        float4 v = ((const float4*)src)[i];
        ((float4*)dst)[i] = make_float4(tf32r(v.x), tf32r(v.y), tf32r(v.z), tf32r(v.w));
    }
}

__global__ void router_kernel(const float* __restrict__ x, const float* __restrict__ Wr) {
    int t = blockIdx.x;
    const float* xr = x + (size_t)t * ND;
    float acc[NE] = {0.f, 0.f, 0.f, 0.f};
    for (int d = threadIdx.x; d < ND; d += blockDim.x) {
        float xv = xr[d];
        float4 w = *(const float4*)(Wr + d * NE);
        acc[0] += xv * w.x; acc[1] += xv * w.y; acc[2] += xv * w.z; acc[3] += xv * w.w;
    }
    __shared__ float sred[NE][8];
    int lane = threadIdx.x & 31, wid = threadIdx.x >> 5;
    #pragma unroll
    for (int e = 0; e < NE; e++) {
        float s = acc[e];
        #pragma unroll
        for (int off = 16; off > 0; off >>= 1) s += __shfl_down_sync(0xffffffffu, s, off);
        if (lane == 0) sred[e][wid] = s;
    }
    __syncthreads();
    if (threadIdx.x == 0) {
        float l[NE];
        #pragma unroll
        for (int e = 0; e < NE; e++) {
            float s = 0.f;
            #pragma unroll
            for (int w = 0; w < 8; w++) s += sred[e][w];
            l[e] = s;
        }
        float mx = fmaxf(fmaxf(l[0], l[1]), fmaxf(l[2], l[3]));
        float ex[NE], ssum = 0.f;
        #pragma unroll
        for (int e = 0; e < NE; e++) { ex[e] = expf(l[e] - mx); ssum += ex[e]; }
        float p[NE];
        #pragma unroll
        for (int e = 0; e < NE; e++) p[e] = ex[e] / ssum;
        int i1 = 0;
        #pragma unroll
        for (int e = 1; e < NE; e++) if (p[e] > p[i1]) i1 = e;
        int i2 = -1;
        #pragma unroll
        for (int e = 0; e < NE; e++)
            if (e != i1 && (i2 < 0 || p[e] > p[i2])) i2 = e;
        #pragma unroll
        for (int e = 0; e < NE; e++)
            g_gatew[e * NT + t] = (e == i1 || e == i2) ? p[e] : 0.f;
    }
}

__global__ void compact_kernel() {
    for (int t = threadIdx.x; t < NT; t += blockDim.x) {
        #pragma unroll
        for (int e = 0; e < NE; e++) {
            if (g_gatew[e * NT + t] > 0.f) {
                int p = atomicAdd(&g_counts[e], 1);
                g_lists[e * NT + p] = t;
            }
        }
    }
}

// ---------------------------------------------------------------------------
// GATE+UP fused GEMM (tf32 mma.sync, cp.async 3-stage pipeline)
// Block tile M=128, N=64 (per matrix), K=16.  8 warps 4x2 -> 32x32 warptile each.
// A tile:  [128 rows][16 k] k-contiguous, row stride 20 words (conflict-free)
// B tiles: [16 k][64 n]  n-contiguous, row stride 72 words (conflict-free)
// ---------------------------------------------------------------------------
#define GU_AF 2560          // 128*20 floats
#define GU_BF 1152          // 16*72 floats
#define GU_STAGEF (GU_AF + 2*GU_BF)           // 4864 floats = 19456 B
#define GU_SMEM (3 * GU_STAGEF * 4)           // 58368 B

__global__ __launch_bounds__(256, 2) void gateup_tc(const float* __restrict__ X) {
    const int e  = blockIdx.z;
    const int Me = g_counts[e];
    const int m0 = blockIdx.x * 128;
    if (m0 >= Me) return;
    const int n0 = blockIdx.y * 64;

    extern __shared__ float smem[];
    const uint32_t sb0 = smem_u32(smem);

    const int tid  = threadIdx.x;
    const int warp = tid >> 5;
    const int lane = tid & 31;
    const int g4   = lane >> 2;
    const int t4   = lane & 3;
    const int wm   = warp >> 1;        // 0..3
    const int wn   = warp & 1;         // 0..1

    // A: thread -> row = tid>>1, k-half = (tid&1)*8; loads k[h..h+3], k[h+4..h+7]
    const int ar = tid >> 1;
    const int ah = (tid & 1) * 8;
    int mrow = m0 + ar; if (mrow >= Me) mrow = Me - 1;
    const float* asrc = X + (size_t)g_lists[e * NT + mrow] * ND + ah;
    const uint32_t adst = sb0 + (ar * 20 + ah) * 4;
    // B: thread -> row = tid>>4 (0..15), col chunk = tid&15
    const int brr = tid >> 4;
    const int bcc = tid & 15;
    const float* bgsrc = g_Wgr + (size_t)e * ND * NF + (size_t)brr * NF + n0 + bcc * 4;
    const float* busrc = g_Wur + (size_t)e * ND * NF + (size_t)brr * NF + n0 + bcc * 4;
    const uint32_t bgdst = sb0 + (GU_AF + brr * 72 + bcc * 4) * 4;
    const uint32_t budst = sb0 + (GU_AF + GU_BF + brr * 72 + bcc * 4) * 4;

    float accG[2][4][4], accU[2][4][4];
    #pragma unroll
    for (int i = 0; i < 2; i++)
        #pragma unroll
        for (int j = 0; j < 4; j++)
            #pragma unroll
            for (int k = 0; k < 4; k++) { accG[i][j][k] = 0.f; accU[i][j][k] = 0.f; }

    const int KT = ND / 16;    // 128
    auto issue = [&](int it) {
        const uint32_t so = (uint32_t)(it % 3) * (GU_STAGEF * 4);
        const size_t ka = (size_t)it * 16;
        cpa16(adst + so,      asrc + ka);        // k[ah .. ah+3]
        cpa16(adst + so + 16, asrc + ka + 4);    // k[ah+4 .. ah+7]
        cpa16(bgdst + so, bgsrc + ka * NF);
        cpa16(budst + so, busrc + ka * NF);
    };

    issue(0); cpa_commit();
    issue(1); cpa_commit();

    for (int it = 0; it < KT; ++it) {
        cpa_wait1();               // groups {it, it+1} committed -> group it complete
        __syncthreads();           // also: all warps done with stage it-1 before overwrite
        if (it + 2 < KT) issue(it + 2);
        cpa_commit();

        const float* As = smem + (it % 3) * GU_STAGEF;
        const float* Bg = As + GU_AF;
        const float* Bu = Bg + GU_BF;

        #pragma unroll
        for (int ks = 0; ks < 16; ks += 8) {
            unsigned a[2][4];
            #pragma unroll
            for (int mi = 0; mi < 2; mi++) {
                const int mb = wm * 32 + mi * 16 + g4;
                a[mi][0] = __float_as_uint(As[(mb    ) * 20 + ks + t4]);
                a[mi][1] = __float_as_uint(As[(mb + 8) * 20 + ks + t4]);
                a[mi][2] = __float_as_uint(As[(mb    ) * 20 + ks + t4 + 4]);
                a[mi][3] = __float_as_uint(As[(mb + 8) * 20 + ks + t4 + 4]);
            }
            #pragma unroll
            for (int ni = 0; ni < 4; ni++) {
                const int nb = wn * 32 + ni * 8 + g4;
                unsigned bg[2] = { __float_as_uint(Bg[(ks + t4) * 72 + nb]),
                                   __float_as_uint(Bg[(ks + t4 + 4) * 72 + nb]) };
                unsigned bu[2] = { __float_as_uint(Bu[(ks + t4) * 72 + nb]),
                                   __float_as_uint(Bu[(ks + t4 + 4) * 72 + nb]) };
                #pragma unroll
                for (int mi = 0; mi < 2; mi++) {
                    mma8(accG[mi][ni], a[mi], bg);
                    mma8(accU[mi][ni], a[mi], bu);
                }
            }
        }
    }

    // epilogue: H = tf32( silu(G)*U )
    #pragma unroll
    for (int mi = 0; mi < 2; mi++) {
        #pragma unroll
        for (int half = 0; half < 2; half++) {
            const int m = m0 + wm * 32 + mi * 16 + g4 + half * 8;
            if (m >= Me) continue;
            float* Hrow = g_H + ((size_t)e * NT + m) * NF + n0 + wn * 32;
            #pragma unroll
            for (int ni = 0; ni < 4; ni++) {
                float gv0 = accG[mi][ni][half * 2],     uv0 = accU[mi][ni][half * 2];
                float gv1 = accG[mi][ni][half * 2 + 1], uv1 = accU[mi][ni][half * 2 + 1];
                float h0 = tf32r(gv0 / (1.f + expf(-gv0)) * uv0);
                float h1 = tf32r(gv1 / (1.f + expf(-gv1)) * uv1);
                *(float2*)(Hrow + ni * 8 + 2 * t4) = make_float2(h0, h1);
            }
        }
    }
}

// ---------------------------------------------------------------------------
// DOWN GEMM + combine (tf32 mma.sync, cp.async 3-stage pipeline)
// Block tile 128x128x16. 8 warps 4x2 -> 32x64 warptile.
// A row stride 20 words, B row stride 136 words.
// ---------------------------------------------------------------------------
#define DN_AF 2560          // 128*20
#define DN_BF 2176          // 16*136
#define DN_STAGEF (DN_AF + DN_BF)             // 4736 floats = 18944 B
#define DN_SMEM (3 * DN_STAGEF * 4)           // 56832 B

__global__ __launch_bounds__(256, 2) void down_tc(float* __restrict__ OUT) {
    const int e  = blockIdx.z;
    const int Me = g_counts[e];
    const int m0 = blockIdx.x * 128;
    if (m0 >= Me) return;
    const int n0 = blockIdx.y * 128;

    extern __shared__ float smem[];
    const uint32_t sb0 = smem_u32(smem);

    const int tid  = threadIdx.x;
    const int warp = tid >> 5;
    const int lane = tid & 31;
    const int g4   = lane >> 2;
    const int t4   = lane & 3;
    const int wm   = warp >> 1;
    const int wn   = warp & 1;

    const int ar = tid >> 1;
    const int ah = (tid & 1) * 8;
    const float* asrc = g_H + ((size_t)e * NT + m0 + ar) * NF + ah;  // rows>=Me read zeros
    const uint32_t adst = sb0 + (ar * 20 + ah) * 4;

    const int br0 = tid >> 5, bc0 = tid & 31;
    const float* bsrc = g_Wdr + (size_t)e * NF * ND + n0;
    const uint32_t bbase = sb0 + DN_AF * 4;

    float acc[2][8][4];
    #pragma unroll
    for (int i = 0; i < 2; i++)
        #pragma unroll
        for (int j = 0; j < 8; j++)
            #pragma unroll
            for (int k = 0; k < 4; k++) acc[i][j][k] = 0.f;

    const int KT = NF / 16;   // 512
    auto issue = [&](int it) {
        const uint32_t so = (uint32_t)(it % 3) * (DN_STAGEF * 4);
        const size_t ka = (size_t)it * 16;
        cpa16(adst + so,      asrc + ka);
        cpa16(adst + so + 16, asrc + ka + 4);
        #pragma unroll
        for (int j = 0; j < 2; j++) {
            const int row = br0 + j * 8;
            cpa16(bbase + so + (row * 136 + bc0 * 4) * 4, bsrc + (ka + row) * ND + bc0 * 4);
        }
    };

    issue(0); cpa_commit();
    issue(1); cpa_commit();

    for (int it = 0; it < KT; ++it) {
        cpa_wait1();
        __syncthreads();
        if (it + 2 < KT) issue(it + 2);
        cpa_commit();

        const float* As = smem + (it % 3) * DN_STAGEF;
        const float* Bs = As + DN_AF;

        #pragma unroll
        for (int ks = 0; ks < 16; ks += 8) {
            unsigned a[2][4];
            #pragma unroll
            for (int mi = 0; mi < 2; mi++) {
                const int mb = wm * 32 + mi * 16 + g4;
                a[mi][0] = __float_as_uint(As[(mb    ) * 20 + ks + t4]);
                a[mi][1] = __float_as_uint(As[(mb + 8) * 20 + ks + t4]);
                a[mi][2] = __float_as_uint(As[(mb    ) * 20 + ks + t4 + 4]);
                a[mi][3] = __float_as_uint(As[(mb + 8) * 20 + ks + t4 + 4]);
            }
            #pragma unroll
            for (int ni = 0; ni < 8; ni++) {
                const int nb = wn * 64 + ni * 8 + g4;
                unsigned b[2] = { __float_as_uint(Bs[(ks + t4) * 136 + nb]),
                                  __float_as_uint(Bs[(ks + t4 + 4) * 136 + nb]) };
                #pragma unroll
                for (int mi = 0; mi < 2; mi++)
                    mma8(acc[mi][ni], a[mi], b);
            }
        }
    }

    #pragma unroll
    for (int mi = 0; mi < 2; mi++) {
        #pragma unroll
        for (int half = 0; half < 2; half++) {
            const int m = m0 + wm * 32 + mi * 16 + g4 + half * 8;
            if (m >= Me) continue;
            const int tok = g_lists[e * NT + m];
            const float w = g_gatew[e * NT + tok];
            float* dst = OUT + (size_t)tok * ND + n0 + wn * 64;
            #pragma unroll
            for (int ni = 0; ni < 8; ni++) {
                atomicAdd(dst + ni * 8 + 2 * t4,     w * acc[mi][ni][half * 2]);
                atomicAdd(dst + ni * 8 + 2 * t4 + 1, w * acc[mi][ni][half * 2 + 1]);
            }
        }
    }
}

// ---------------------------------------------------------------------------
extern "C" void kernel_launch(void* const* d_in, const int* in_sizes, int n_in,
                              void* d_out, int out_size) {
    const float* x  = (const float*)d_in[0];
    const float* Wr = (const float*)d_in[1];
    const float* Wg = (const float*)d_in[2];
    const float* Wu = (const float*)d_in[3];
    const float* Wd = (const float*)d_in[4];
    float* out = (float*)d_out;

    cudaFuncSetAttribute(gateup_tc, cudaFuncAttributeMaxDynamicSharedMemorySize, GU_SMEM);
    cudaFuncSetAttribute(down_tc,   cudaFuncAttributeMaxDynamicSharedMemorySize, DN_SMEM);

    float* wgr; cudaGetSymbolAddress((void**)&wgr, g_Wgr);
    float* wur; cudaGetSymbolAddress((void**)&wur, g_Wur);
    float* wdr; cudaGetSymbolAddress((void**)&wdr, g_Wdr);
    float* xr;  cudaGetSymbolAddress((void**)&xr,  g_Xr);

    zero_kernel<<<2048, 256>>>(out);
    router_kernel<<<NT, 256>>>(x, Wr);
    compact_kernel<<<1, 256>>>();

    round_copy<<<2048, 256>>>(x,  xr,  (size_t)NT * ND / 4);
    round_copy<<<4096, 256>>>(Wg, wgr, (size_t)NE * ND * NF / 4);
    round_copy<<<4096, 256>>>(Wu, wur, (size_t)NE * ND * NF / 4);
    round_copy<<<4096, 256>>>(Wd, wdr, (size_t)NE * NF * ND / 4);

    gateup_tc<<<dim3(NT/128, NF/64, NE), 256, GU_SMEM>>>(xr);
    down_tc  <<<dim3(NT/128, ND/128, NE), 256, DN_SMEM>>>(out);
}

// round 6
// speedup vs baseline: 5.2074x; 1.0379x over previous
#include <cuda_runtime.h>
#include <math.h>
#include <stdint.h>

#define NB 2
#define NS 1024
#define NT (NB*NS)      // 2048 tokens
#define ND 2048
#define NF 8192
#define NE 4

// ---------------- persistent scratch (device globals) ----------------------
__device__ float g_gatew[NE*NT];
__device__ int   g_counts[NE];
__device__ int   g_lists[NE*NT];
__device__ float g_H [(size_t)NE*NT*NF];   // H = silu(G)*U, tf32-rounded; rows>=Me stay 0
__device__ float g_Xr[(size_t)NT*ND];      // x, tf32-rounded

// ---------------- helpers ---------------------------------------------------
__device__ __forceinline__ uint32_t smem_u32(const void* p) {
    uint32_t a;
    asm("{ .reg .u64 t; cvta.to.shared.u64 t, %1; cvt.u32.u64 %0, t; }" : "=r"(a) : "l"(p));
    return a;
}
__device__ __forceinline__ unsigned f2tf(float f) {
    unsigned u; asm("cvt.rna.tf32.f32 %0, %1;" : "=r"(u) : "f"(f)); return u;
}
__device__ __forceinline__ float tf32r(float f) { return __uint_as_float(f2tf(f)); }

__device__ __forceinline__ void cpa16(uint32_t dst, const float* src) {
    asm volatile("cp.async.cg.shared.global [%0], [%1], 16;" :: "r"(dst), "l"(src));
}
__device__ __forceinline__ void cpa_commit() { asm volatile("cp.async.commit_group;"); }
__device__ __forceinline__ void cpa_wait1()  { asm volatile("cp.async.wait_group 1;"); }

__device__ __forceinline__ void mma8(float c[4], const unsigned a[4], const unsigned b[2]) {
    asm volatile(
        "mma.sync.aligned.m16n8k8.row.col.f32.tf32.tf32.f32 "
        "{%0,%1,%2,%3}, {%4,%5,%6,%7}, {%8,%9}, {%0,%1,%2,%3};"
        : "+f"(c[0]), "+f"(c[1]), "+f"(c[2]), "+f"(c[3])
        : "r"(a[0]), "r"(a[1]), "r"(a[2]), "r"(a[3]), "r"(b[0]), "r"(b[1]));
}

// ---------------- trivial kernels -------------------------------------------
__global__ void zero_kernel(float* __restrict__ out) {
    size_t n = (size_t)NT * ND;
    for (size_t i = blockIdx.x * (size_t)blockDim.x + threadIdx.x; i < n;
         i += (size_t)gridDim.x * blockDim.x) out[i] = 0.f;
    if (blockIdx.x == 0 && threadIdx.x < NE) g_counts[threadIdx.x] = 0;
}

__global__ void round_copy(const float* __restrict__ src, float* __restrict__ dst, size_t n4) {
    for (size_t i = blockIdx.x * (size_t)blockDim.x + threadIdx.x; i < n4;
         i += (size_t)gridDim.x * blockDim.x) {
        float4 v = ((const float4*)src)[i];
        ((float4*)dst)[i] = make_float4(tf32r(v.x), tf32r(v.y), tf32r(v.z), tf32r(v.w));
    }
}

__global__ void router_kernel(const float* __restrict__ x, const float* __restrict__ Wr) {
    int t = blockIdx.x;
    const float* xr = x + (size_t)t * ND;
    float acc[NE] = {0.f, 0.f, 0.f, 0.f};
    for (int d = threadIdx.x; d < ND; d += blockDim.x) {
        float xv = xr[d];
        float4 w = *(const float4*)(Wr + d * NE);
        acc[0] += xv * w.x; acc[1] += xv * w.y; acc[2] += xv * w.z; acc[3] += xv * w.w;
    }
    __shared__ float sred[NE][8];
    int lane = threadIdx.x & 31, wid = threadIdx.x >> 5;
    #pragma unroll
    for (int e = 0; e < NE; e++) {
        float s = acc[e];
        #pragma unroll
        for (int off = 16; off > 0; off >>= 1) s += __shfl_down_sync(0xffffffffu, s, off);
        if (lane == 0) sred[e][wid] = s;
    }
    __syncthreads();
    if (threadIdx.x == 0) {
        float l[NE];
        #pragma unroll
        for (int e = 0; e < NE; e++) {
            float s = 0.f;
            #pragma unroll
            for (int w = 0; w < 8; w++) s += sred[e][w];
            l[e] = s;
        }
        float mx = fmaxf(fmaxf(l[0], l[1]), fmaxf(l[2], l[3]));
        float ex[NE], ssum = 0.f;
        #pragma unroll
        for (int e = 0; e < NE; e++) { ex[e] = expf(l[e] - mx); ssum += ex[e]; }
        float p[NE];
        #pragma unroll
        for (int e = 0; e < NE; e++) p[e] = ex[e] / ssum;
        int i1 = 0;
        #pragma unroll
        for (int e = 1; e < NE; e++) if (p[e] > p[i1]) i1 = e;
        int i2 = -1;
        #pragma unroll
        for (int e = 0; e < NE; e++)
            if (e != i1 && (i2 < 0 || p[e] > p[i2])) i2 = e;
        #pragma unroll
        for (int e = 0; e < NE; e++)
            g_gatew[e * NT + t] = (e == i1 || e == i2) ? p[e] : 0.f;
    }
}

__global__ void compact_kernel() {
    for (int t = threadIdx.x; t < NT; t += blockDim.x) {
        #pragma unroll
        for (int e = 0; e < NE; e++) {
            if (g_gatew[e * NT + t] > 0.f) {
                int p = atomicAdd(&g_counts[e], 1);
                g_lists[e * NT + p] = t;
            }
        }
    }
}

// ---------------------------------------------------------------------------
// GATE+UP fused GEMM (tf32 mma.sync, cp.async 3-stage pipeline)
// Block tile M=128, N=64 (per matrix), K=16.  8 warps 4x2 -> 32x32 warptile each.
// A tile:  [128 rows][16 k] k-contiguous, row stride 20 words (conflict-free)
// B tiles: [16 k][64 n]  n-contiguous, row stride 72 words (conflict-free)
// A is pre-rounded tf32 (g_Xr); B is RAW fp32, rounded RNA at fragment load.
// ---------------------------------------------------------------------------
#define GU_AF 2560          // 128*20 floats
#define GU_BF 1152          // 16*72 floats
#define GU_STAGEF (GU_AF + 2*GU_BF)           // 4864 floats = 19456 B
#define GU_SMEM (3 * GU_STAGEF * 4)           // 58368 B

__global__ __launch_bounds__(256, 2) void gateup_tc(const float* __restrict__ X,
                                                    const float* __restrict__ Wg,
                                                    const float* __restrict__ Wu) {
    const int e  = blockIdx.z;
    const int Me = g_counts[e];
    const int m0 = blockIdx.x * 128;
    if (m0 >= Me) return;
    const int n0 = blockIdx.y * 64;

    extern __shared__ float smem[];
    const uint32_t sb0 = smem_u32(smem);

    const int tid  = threadIdx.x;
    const int warp = tid >> 5;
    const int lane = tid & 31;
    const int g4   = lane >> 2;
    const int t4   = lane & 3;
    const int wm   = warp >> 1;        // 0..3
    const int wn   = warp & 1;         // 0..1

    const int ar = tid >> 1;
    const int ah = (tid & 1) * 8;
    int mrow = m0 + ar; if (mrow >= Me) mrow = Me - 1;
    const float* asrc = X + (size_t)g_lists[e * NT + mrow] * ND + ah;
    const uint32_t adst = sb0 + (ar * 20 + ah) * 4;
    const int brr = tid >> 4;
    const int bcc = tid & 15;
    const float* bgsrc = Wg + (size_t)e * ND * NF + (size_t)brr * NF + n0 + bcc * 4;
    const float* busrc = Wu + (size_t)e * ND * NF + (size_t)brr * NF + n0 + bcc * 4;
    const uint32_t bgdst = sb0 + (GU_AF + brr * 72 + bcc * 4) * 4;
    const uint32_t budst = sb0 + (GU_AF + GU_BF + brr * 72 + bcc * 4) * 4;

    float accG[2][4][4], accU[2][4][4];
    #pragma unroll
    for (int i = 0; i < 2; i++)
        #pragma unroll
        for (int j = 0; j < 4; j++)
            #pragma unroll
            for (int k = 0; k < 4; k++) { accG[i][j][k] = 0.f; accU[i][j][k] = 0.f; }

    const int KT = ND / 16;    // 128
    auto issue = [&](int it) {
        const uint32_t so = (uint32_t)(it % 3) * (GU_STAGEF * 4);
        const size_t ka = (size_t)it * 16;
        cpa16(adst + so,      asrc + ka);
        cpa16(adst + so + 16, asrc + ka + 4);
        cpa16(bgdst + so, bgsrc + ka * NF);
        cpa16(budst + so, busrc + ka * NF);
    };

    issue(0); cpa_commit();
    issue(1); cpa_commit();

    for (int it = 0; it < KT; ++it) {
        cpa_wait1();               // groups {it, it+1} pending -> group it complete
        __syncthreads();
        if (it + 2 < KT) issue(it + 2);
        cpa_commit();

        const float* As = smem + (it % 3) * GU_STAGEF;
        const float* Bg = As + GU_AF;
        const float* Bu = Bg + GU_BF;

        #pragma unroll
        for (int ks = 0; ks < 16; ks += 8) {
            unsigned a[2][4];
            #pragma unroll
            for (int mi = 0; mi < 2; mi++) {
                const int mb = wm * 32 + mi * 16 + g4;
                a[mi][0] = __float_as_uint(As[(mb    ) * 20 + ks + t4]);
                a[mi][1] = __float_as_uint(As[(mb + 8) * 20 + ks + t4]);
                a[mi][2] = __float_as_uint(As[(mb    ) * 20 + ks + t4 + 4]);
                a[mi][3] = __float_as_uint(As[(mb + 8) * 20 + ks + t4 + 4]);
            }
            #pragma unroll
            for (int ni = 0; ni < 4; ni++) {
                const int nb = wn * 32 + ni * 8 + g4;
                unsigned bg[2] = { f2tf(Bg[(ks + t4) * 72 + nb]),
                                   f2tf(Bg[(ks + t4 + 4) * 72 + nb]) };
                unsigned bu[2] = { f2tf(Bu[(ks + t4) * 72 + nb]),
                                   f2tf(Bu[(ks + t4 + 4) * 72 + nb]) };
                #pragma unroll
                for (int mi = 0; mi < 2; mi++) {
                    mma8(accG[mi][ni], a[mi], bg);
                    mma8(accU[mi][ni], a[mi], bu);
                }
            }
        }
    }

    // epilogue: H = tf32( silu(G)*U )
    #pragma unroll
    for (int mi = 0; mi < 2; mi++) {
        #pragma unroll
        for (int half = 0; half < 2; half++) {
            const int m = m0 + wm * 32 + mi * 16 + g4 + half * 8;
            if (m >= Me) continue;
            float* Hrow = g_H + ((size_t)e * NT + m) * NF + n0 + wn * 32;
            #pragma unroll
            for (int ni = 0; ni < 4; ni++) {
                float gv0 = accG[mi][ni][half * 2],     uv0 = accU[mi][ni][half * 2];
                float gv1 = accG[mi][ni][half * 2 + 1], uv1 = accU[mi][ni][half * 2 + 1];
                float h0 = tf32r(gv0 / (1.f + expf(-gv0)) * uv0);
                float h1 = tf32r(gv1 / (1.f + expf(-gv1)) * uv1);
                *(float2*)(Hrow + ni * 8 + 2 * t4) = make_float2(h0, h1);
            }
        }
    }
}

// ---------------------------------------------------------------------------
// DOWN GEMM + combine (tf32 mma.sync, cp.async 3-stage pipeline)
// Block tile 128x128x16. 8 warps 4x2 -> 32x64 warptile.
// A (H) pre-rounded tf32; B (Wd) RAW fp32, rounded RNA at fragment load.
// ---------------------------------------------------------------------------
#define DN_AF 2560          // 128*20
#define DN_BF 2176          // 16*136
#define DN_STAGEF (DN_AF + DN_BF)             // 4736 floats = 18944 B
#define DN_SMEM (3 * DN_STAGEF * 4)           // 56832 B

__global__ __launch_bounds__(256, 2) void down_tc(const float* __restrict__ Wd,
                                                  float* __restrict__ OUT) {
    const int e  = blockIdx.z;
    const int Me = g_counts[e];
    const int m0 = blockIdx.x * 128;
    if (m0 >= Me) return;
    const int n0 = blockIdx.y * 128;

    extern __shared__ float smem[];
    const uint32_t sb0 = smem_u32(smem);

    const int tid  = threadIdx.x;
    const int warp = tid >> 5;
    const int lane = tid & 31;
    const int g4   = lane >> 2;
    const int t4   = lane & 3;
    const int wm   = warp >> 1;
    const int wn   = warp & 1;

    const int ar = tid >> 1;
    const int ah = (tid & 1) * 8;
    const float* asrc = g_H + ((size_t)e * NT + m0 + ar) * NF + ah;  // rows>=Me read zeros
    const uint32_t adst = sb0 + (ar * 20 + ah) * 4;

    const int br0 = tid >> 5, bc0 = tid & 31;
    const float* bsrc = Wd + (size_t)e * NF * ND + n0;
    const uint32_t bbase = sb0 + DN_AF * 4;

    float acc[2][8][4];
    #pragma unroll
    for (int i = 0; i < 2; i++)
        #pragma unroll
        for (int j = 0; j < 8; j++)
            #pragma unroll
            for (int k = 0; k < 4; k++) acc[i][j][k] = 0.f;

    const int KT = NF / 16;   // 512
    auto issue = [&](int it) {
        const uint32_t so = (uint32_t)(it % 3) * (DN_STAGEF * 4);
        const size_t ka = (size_t)it * 16;
        cpa16(adst + so,      asrc + ka);
        cpa16(adst + so + 16, asrc + ka + 4);
        #pragma unroll
        for (int j = 0; j < 2; j++) {
            const int row = br0 + j * 8;
            cpa16(bbase + so + (row * 136 + bc0 * 4) * 4, bsrc + (ka + row) * ND + bc0 * 4);
        }
    };

    issue(0); cpa_commit();
    issue(1); cpa_commit();

    for (int it = 0; it < KT; ++it) {
        cpa_wait1();
        __syncthreads();
        if (it + 2 < KT) issue(it + 2);
        cpa_commit();

        const float* As = smem + (it % 3) * DN_STAGEF;
        const float* Bs = As + DN_AF;

        #pragma unroll
        for (int ks = 0; ks < 16; ks += 8) {
            unsigned a[2][4];
            #pragma unroll
            for (int mi = 0; mi < 2; mi++) {
                const int mb = wm * 32 + mi * 16 + g4;
                a[mi][0] = __float_as_uint(As[(mb    ) * 20 + ks + t4]);
                a[mi][1] = __float_as_uint(As[(mb + 8) * 20 + ks + t4]);
                a[mi][2] = __float_as_uint(As[(mb    ) * 20 + ks + t4 + 4]);
                a[mi][3] = __float_as_uint(As[(mb + 8) * 20 + ks + t4 + 4]);
            }
            #pragma unroll
            for (int ni = 0; ni < 8; ni++) {
                const int nb = wn * 64 + ni * 8 + g4;
                unsigned b[2] = { f2tf(Bs[(ks + t4) * 136 + nb]),
                                  f2tf(Bs[(ks + t4 + 4) * 136 + nb]) };
                #pragma unroll
                for (int mi = 0; mi < 2; mi++)
                    mma8(acc[mi][ni], a[mi], b);
            }
        }
    }

    #pragma unroll
    for (int mi = 0; mi < 2; mi++) {
        #pragma unroll
        for (int half = 0; half < 2; half++) {
            const int m = m0 + wm * 32 + mi * 16 + g4 + half * 8;
            if (m >= Me) continue;
            const int tok = g_lists[e * NT + m];
            const float w = g_gatew[e * NT + tok];
            float* dst = OUT + (size_t)tok * ND + n0 + wn * 64;
            #pragma unroll
            for (int ni = 0; ni < 8; ni++) {
                atomicAdd(dst + ni * 8 + 2 * t4,     w * acc[mi][ni][half * 2]);
                atomicAdd(dst + ni * 8 + 2 * t4 + 1, w * acc[mi][ni][half * 2 + 1]);
            }
        }
    }
}

// ---------------------------------------------------------------------------
extern "C" void kernel_launch(void* const* d_in, const int* in_sizes, int n_in,
                              void* d_out, int out_size) {
    const float* x  = (const float*)d_in[0];
    const float* Wr = (const float*)d_in[1];
    const float* Wg = (const float*)d_in[2];
    const float* Wu = (const float*)d_in[3];
    const float* Wd = (const float*)d_in[4];
    float* out = (float*)d_out;

    cudaFuncSetAttribute(gateup_tc, cudaFuncAttributeMaxDynamicSharedMemorySize, GU_SMEM);
    cudaFuncSetAttribute(down_tc,   cudaFuncAttributeMaxDynamicSharedMemorySize, DN_SMEM);

    float* xr;  cudaGetSymbolAddress((void**)&xr, g_Xr);

    zero_kernel<<<2048, 256>>>(out);
    router_kernel<<<NT, 256>>>(x, Wr);
    compact_kernel<<<1, 256>>>();
    round_copy<<<2048, 256>>>(x, xr, (size_t)NT * ND / 4);

    gateup_tc<<<dim3(NT/128, NF/64, NE), 256, GU_SMEM>>>(xr, Wg, Wu);
    down_tc  <<<dim3(NT/128, ND/128, NE), 256, DN_SMEM>>>(Wd, out);
}